// round 2
// baseline (speedup 1.0000x reference)
#include <cuda_runtime.h>

// Problem constants
#define BB 8
#define TT 1024
#define CC 768
#define HH 12
#define DD 64
#define NTOK (BB * TT)      // 8192
#define NQKV (3 * CC)       // 2304

// Scratch (device globals; no runtime allocation allowed)
__device__ float g_q[BB * HH * TT * DD];   // [B,H,T,D], pre-scaled by 1/sqrt(D)
__device__ float g_k[BB * HH * TT * DD];
__device__ float g_v[BB * HH * TT * DD];
__device__ float g_y[BB * TT * CC];        // attention output, [B,T,C]

// ---------------------------------------------------------------------------
// Kernel 1: QKV GEMM.  qkv = x @ w_qkv + b_qkv, scattered into g_q/g_k/g_v
// in [B,H,T,D] layout.  q is pre-scaled by 0.125 = 1/sqrt(64).
// Tiling: 128x128x16, 256 threads, 8x8 per thread (split 4+4 for vector LDS).
// ---------------------------------------------------------------------------
__global__ __launch_bounds__(256) void qkv_gemm_kernel(
    const float* __restrict__ x,
    const float* __restrict__ w,
    const float* __restrict__ bias)
{
    __shared__ __align__(16) float As[16][132];  // transposed x tile, padded
    __shared__ __align__(16) float Bs[16][128];  // w tile

    const int tid = threadIdx.x;
    const int tx = tid & 15;
    const int ty = tid >> 4;
    const int m0 = blockIdx.y * 128;
    const int n0 = blockIdx.x * 128;

    float acc[8][8];
#pragma unroll
    for (int i = 0; i < 8; i++)
#pragma unroll
        for (int j = 0; j < 8; j++) acc[i][j] = 0.0f;

    for (int k0 = 0; k0 < CC; k0 += 16) {
        // Load x tile [128 x 16] -> As transposed
#pragma unroll
        for (int i = 0; i < 2; i++) {
            int f = tid + i * 256;
            int row = f >> 2;
            int c4 = (f & 3) << 2;
            float4 v = *(const float4*)(x + (size_t)(m0 + row) * CC + k0 + c4);
            As[c4 + 0][row] = v.x;
            As[c4 + 1][row] = v.y;
            As[c4 + 2][row] = v.z;
            As[c4 + 3][row] = v.w;
        }
        // Load w tile [16 x 128] -> Bs
#pragma unroll
        for (int i = 0; i < 2; i++) {
            int f = tid + i * 256;
            int row = f >> 5;
            int c4 = (f & 31) << 2;
            *(float4*)&Bs[row][c4] =
                *(const float4*)(w + (size_t)(k0 + row) * NQKV + n0 + c4);
        }
        __syncthreads();

#pragma unroll
        for (int kk = 0; kk < 16; kk++) {
            float a[8], b[8];
            *(float4*)&a[0] = *(const float4*)&As[kk][ty * 4];
            *(float4*)&a[4] = *(const float4*)&As[kk][64 + ty * 4];
            *(float4*)&b[0] = *(const float4*)&Bs[kk][tx * 4];
            *(float4*)&b[4] = *(const float4*)&Bs[kk][64 + tx * 4];
#pragma unroll
            for (int i = 0; i < 8; i++)
#pragma unroll
                for (int j = 0; j < 8; j++) acc[i][j] += a[i] * b[j];
        }
        __syncthreads();
    }

    // Epilogue: bias + scatter to [B,H,T,D].  Each 128-col block is entirely
    // within one of the q/k/v regions (768 = 6*128).
    const int region = n0 / CC;  // 0=q, 1=k, 2=v
    const int cbase = n0 - region * CC;
    float* dst = (region == 0) ? g_q : (region == 1) ? g_k : g_v;
    const float scale = (region == 0) ? 0.125f : 1.0f;

#pragma unroll
    for (int i = 0; i < 8; i++) {
        int row = (i < 4) ? (ty * 4 + i) : (64 + ty * 4 + (i - 4));
        int m = m0 + row;
        int bidx = m >> 10;       // / 1024
        int t = m & 1023;
#pragma unroll
        for (int j = 0; j < 8; j++) {
            int col = (j < 4) ? (tx * 4 + j) : (64 + tx * 4 + (j - 4));
            int c = cbase + col;
            int h = c >> 6;
            int d = c & 63;
            float val = (acc[i][j] + bias[n0 + col]) * scale;
            dst[((size_t)(bidx * HH + h) * TT + t) * DD + d] = val;
        }
    }
}

// ---------------------------------------------------------------------------
// Kernel 2: causal flash attention.  One block per (head, 64-row Q tile).
// 256 threads; thread (rg = tid>>4, tc = tid&15) owns rows {rg+16a} and
// cols {tc+16cc}, a,cc in 0..3  -> 4x4 micro-tile, 8 LDS per 16 FFMA.
// Smem tiles XOR-swizzled by (row & 15) so all hot LDS are conflict-free
// with per-thread-constant xor terms.  P reuses the K buffer (48KB total).
// ---------------------------------------------------------------------------
__global__ __launch_bounds__(256) void attn_kernel()
{
    __shared__ __align__(16) float Qs[4096];
    __shared__ __align__(16) float KPs[4096];  // K tile, then P tile
    __shared__ __align__(16) float Vs[4096];

    const int tid = threadIdx.x;
    const int rg = tid >> 4;   // 0..15
    const int tc = tid & 15;   // 0..15
    const int qt = blockIdx.x; // 0..15 (query tile)
    const int bh = blockIdx.y; // 0..95
    const int q0 = qt * 64;

    const float* Qg = g_q + (size_t)bh * (TT * DD);
    const float* Kg = g_k + (size_t)bh * (TT * DD);
    const float* Vg = g_v + (size_t)bh * (TT * DD);

    // Load Q tile (swizzled: element (r,d) at r*64 + (d ^ (r&15)))
#pragma unroll
    for (int i = 0; i < 4; i++) {
        int f = tid + i * 256;
        int rr = f >> 4;
        int c4 = (f & 15) << 2;
        float4 v = *(const float4*)(Qg + (size_t)(q0 + rr) * DD + c4);
        int sw = rr & 15;
        int base = rr * 64;
        Qs[base + ((c4 + 0) ^ sw)] = v.x;
        Qs[base + ((c4 + 1) ^ sw)] = v.y;
        Qs[base + ((c4 + 2) ^ sw)] = v.z;
        Qs[base + ((c4 + 3) ^ sw)] = v.w;
    }

    float o[4][4];
    float m_r[4], l_r[4];
#pragma unroll
    for (int a = 0; a < 4; a++) {
        m_r[a] = -1e30f;
        l_r[a] = 0.0f;
#pragma unroll
        for (int ii = 0; ii < 4; ii++) o[a][ii] = 0.0f;
    }

    for (int j = 0; j <= qt; j++) {
        const int k0 = j * 64;
        __syncthreads();  // prior iteration done with KPs/Vs; Q load visible
        // Load K (swizzled) and V (plain) tiles
#pragma unroll
        for (int i = 0; i < 4; i++) {
            int f = tid + i * 256;
            int rr = f >> 4;
            int c4 = (f & 15) << 2;
            float4 kv = *(const float4*)(Kg + (size_t)(k0 + rr) * DD + c4);
            int sw = rr & 15;
            int base = rr * 64;
            KPs[base + ((c4 + 0) ^ sw)] = kv.x;
            KPs[base + ((c4 + 1) ^ sw)] = kv.y;
            KPs[base + ((c4 + 2) ^ sw)] = kv.z;
            KPs[base + ((c4 + 3) ^ sw)] = kv.w;
            *(float4*)(Vs + base + c4) =
                *(const float4*)(Vg + (size_t)(k0 + rr) * DD + c4);
        }
        __syncthreads();

        // S = Q K^T  (Q already scaled)
        float s[4][4];
#pragma unroll
        for (int a = 0; a < 4; a++)
#pragma unroll
            for (int cc = 0; cc < 4; cc++) s[a][cc] = 0.0f;

#pragma unroll 8
        for (int d = 0; d < 64; d++) {
            const int dq = d ^ rg;
            const int dk = d ^ tc;
            float qv[4], kv_[4];
#pragma unroll
            for (int a = 0; a < 4; a++) qv[a] = Qs[(rg + 16 * a) * 64 + dq];
#pragma unroll
            for (int cc = 0; cc < 4; cc++) kv_[cc] = KPs[(tc + 16 * cc) * 64 + dk];
#pragma unroll
            for (int a = 0; a < 4; a++)
#pragma unroll
                for (int cc = 0; cc < 4; cc++) s[a][cc] += qv[a] * kv_[cc];
        }
        __syncthreads();  // everyone done reading K before P overwrites it

        // Causal mask (diagonal tile only; q0 == k0 there)
        if (j == qt) {
#pragma unroll
            for (int a = 0; a < 4; a++) {
                int row = rg + 16 * a;
#pragma unroll
                for (int cc = 0; cc < 4; cc++) {
                    int col = tc + 16 * cc;
                    if (col > row) s[a][cc] = -1e30f;
                }
            }
        }

        // Online softmax: each row owned by 16 consecutive lanes
#pragma unroll
        for (int a = 0; a < 4; a++) {
            float mx = fmaxf(fmaxf(s[a][0], s[a][1]), fmaxf(s[a][2], s[a][3]));
#pragma unroll
            for (int off = 1; off < 16; off <<= 1)
                mx = fmaxf(mx, __shfl_xor_sync(0xffffffffu, mx, off));
            float m_new = fmaxf(m_r[a], mx);
            float corr = __expf(m_r[a] - m_new);
            float sum = 0.0f;
#pragma unroll
            for (int cc = 0; cc < 4; cc++) {
                float p = __expf(s[a][cc] - m_new);
                s[a][cc] = p;
                sum += p;
            }
#pragma unroll
            for (int off = 1; off < 16; off <<= 1)
                sum += __shfl_xor_sync(0xffffffffu, sum, off);
            l_r[a] = l_r[a] * corr + sum;
            m_r[a] = m_new;
#pragma unroll
            for (int ii = 0; ii < 4; ii++) o[a][ii] *= corr;
        }

        // Write P into KPs (same swizzle; row group stays inside one warp)
#pragma unroll
        for (int a = 0; a < 4; a++) {
            int base = (rg + 16 * a) * 64;
#pragma unroll
            for (int cc = 0; cc < 4; cc++) {
                int col = tc + 16 * cc;
                KPs[base + (col ^ rg)] = s[a][cc];
            }
        }
        __syncwarp();  // P row r is written+read by the same 16-lane group

        // O += P @ V
#pragma unroll 8
        for (int c = 0; c < 64; c++) {
            const int cs = c ^ rg;
            float pv[4], vv[4];
#pragma unroll
            for (int a = 0; a < 4; a++) pv[a] = KPs[(rg + 16 * a) * 64 + cs];
#pragma unroll
            for (int ii = 0; ii < 4; ii++) vv[ii] = Vs[c * 64 + tc + 16 * ii];
#pragma unroll
            for (int a = 0; a < 4; a++)
#pragma unroll
                for (int ii = 0; ii < 4; ii++) o[a][ii] += pv[a] * vv[ii];
        }
    }

    // Epilogue: normalize, store to g_y in [B,T,C]
    const int bidx = bh / HH;
    const int h = bh % HH;
#pragma unroll
    for (int a = 0; a < 4; a++) {
        int row = rg + 16 * a;
        int t = q0 + row;
        float inv_l = 1.0f / l_r[a];
        float* dst = g_y + ((size_t)(bidx * TT + t)) * CC + h * DD;
#pragma unroll
        for (int ii = 0; ii < 4; ii++)
            dst[tc + 16 * ii] = o[a][ii] * inv_l;
    }
}

// ---------------------------------------------------------------------------
// Kernel 3: output projection.  out = g_y @ w_proj + b_proj
// Same SGEMM structure as kernel 1; plain row-major store.
// ---------------------------------------------------------------------------
__global__ __launch_bounds__(256) void proj_gemm_kernel(
    const float* __restrict__ w,
    const float* __restrict__ bias,
    float* __restrict__ out)
{
    __shared__ __align__(16) float As[16][132];
    __shared__ __align__(16) float Bs[16][128];

    const int tid = threadIdx.x;
    const int tx = tid & 15;
    const int ty = tid >> 4;
    const int m0 = blockIdx.y * 128;
    const int n0 = blockIdx.x * 128;

    float acc[8][8];
#pragma unroll
    for (int i = 0; i < 8; i++)
#pragma unroll
        for (int j = 0; j < 8; j++) acc[i][j] = 0.0f;

    for (int k0 = 0; k0 < CC; k0 += 16) {
#pragma unroll
        for (int i = 0; i < 2; i++) {
            int f = tid + i * 256;
            int row = f >> 2;
            int c4 = (f & 3) << 2;
            float4 v = *(const float4*)(g_y + (size_t)(m0 + row) * CC + k0 + c4);
            As[c4 + 0][row] = v.x;
            As[c4 + 1][row] = v.y;
            As[c4 + 2][row] = v.z;
            As[c4 + 3][row] = v.w;
        }
#pragma unroll
        for (int i = 0; i < 2; i++) {
            int f = tid + i * 256;
            int row = f >> 5;
            int c4 = (f & 31) << 2;
            *(float4*)&Bs[row][c4] =
                *(const float4*)(w + (size_t)(k0 + row) * CC + n0 + c4);
        }
        __syncthreads();

#pragma unroll
        for (int kk = 0; kk < 16; kk++) {
            float a[8], b[8];
            *(float4*)&a[0] = *(const float4*)&As[kk][ty * 4];
            *(float4*)&a[4] = *(const float4*)&As[kk][64 + ty * 4];
            *(float4*)&b[0] = *(const float4*)&Bs[kk][tx * 4];
            *(float4*)&b[4] = *(const float4*)&Bs[kk][64 + tx * 4];
#pragma unroll
            for (int i = 0; i < 8; i++)
#pragma unroll
                for (int j = 0; j < 8; j++) acc[i][j] += a[i] * b[j];
        }
        __syncthreads();
    }

#pragma unroll
    for (int i = 0; i < 8; i++) {
        int row = (i < 4) ? (ty * 4 + i) : (64 + ty * 4 + (i - 4));
        int m = m0 + row;
#pragma unroll
        for (int j = 0; j < 8; j++) {
            int col = (j < 4) ? (tx * 4 + j) : (64 + tx * 4 + (j - 4));
            out[(size_t)m * CC + n0 + col] = acc[i][j] + bias[n0 + col];
        }
    }
}

// ---------------------------------------------------------------------------
extern "C" void kernel_launch(void* const* d_in, const int* in_sizes, int n_in,
                              void* d_out, int out_size)
{
    const float* x      = (const float*)d_in[0];
    const float* w_qkv  = (const float*)d_in[1];
    const float* b_qkv  = (const float*)d_in[2];
    const float* w_proj = (const float*)d_in[3];
    const float* b_proj = (const float*)d_in[4];
    float* out = (float*)d_out;

    qkv_gemm_kernel<<<dim3(NQKV / 128, NTOK / 128), 256>>>(x, w_qkv, b_qkv);
    attn_kernel<<<dim3(TT / 64, BB * HH), 256>>>();
    proj_gemm_kernel<<<dim3(CC / 128, NTOK / 128), 256>>>(w_proj, b_proj, out);
}

// round 8
// speedup vs baseline: 1.0084x; 1.0084x over previous
#include <cuda_runtime.h>
#include <cstdint>

// Problem constants
#define BB 8
#define TT 1024
#define CC 768
#define HH 12
#define DD 64
#define NTOK (BB * TT)      // 8192
#define NQKV (3 * CC)       // 2304

// Scratch (device globals; no runtime allocation allowed)
__device__ float g_q[BB * HH * TT * DD];   // [B,H,T,D], q pre-scaled by 1/8
__device__ float g_k[BB * HH * TT * DD];
__device__ float g_v[BB * HH * TT * DD];
__device__ float g_y[BB * TT * CC];        // attention output (tf32-rounded)
__device__ float g_xc[NTOK * CC];          // x, tf32-rounded
__device__ float g_wqc[CC * NQKV];         // w_qkv, tf32-rounded
__device__ float g_wpc[CC * CC];           // w_proj, tf32-rounded

// ---------------------------------------------------------------------------
// Helpers (all compute_80-level PTX; no sm_103a-only features)
// ---------------------------------------------------------------------------
__device__ __forceinline__ uint32_t smem_u32(const void* p) {
    uint32_t a;
    asm("{ .reg .u64 t; cvta.to.shared.u64 t, %1; cvt.u32.u64 %0, t; }"
        : "=r"(a) : "l"(p));
    return a;
}
__device__ __forceinline__ uint32_t tf32_bits(float x) {
    uint32_t r;
    asm("cvt.rna.tf32.f32 %0, %1;" : "=r"(r) : "f"(x));
    return r;
}
__device__ __forceinline__ void cp_async16(uint32_t dst, const void* src) {
    asm volatile("cp.async.ca.shared.global [%0], [%1], 16;"
                 :: "r"(dst), "l"(src));
}
#define CP_COMMIT() asm volatile("cp.async.commit_group;" ::: "memory")
#define CP_WAIT(n)  asm volatile("cp.async.wait_group %0;" :: "n"(n) : "memory")

// m16n8k8 tf32 mma: D += A*B, fp32 accumulate.
__device__ __forceinline__ void mma_tf32(float* d, const uint32_t* a,
                                         const uint32_t* b) {
    asm volatile(
        "mma.sync.aligned.m16n8k8.row.col.f32.tf32.tf32.f32 "
        "{%0,%1,%2,%3}, {%4,%5,%6,%7}, {%8,%9}, {%0,%1,%2,%3};"
        : "+f"(d[0]), "+f"(d[1]), "+f"(d[2]), "+f"(d[3])
        : "r"(a[0]), "r"(a[1]), "r"(a[2]), "r"(a[3]),
          "r"(b[0]), "r"(b[1]));
}

// ---------------------------------------------------------------------------
// Elementwise tf32 rounding pass (RNA), vectorized.
// which: 0 -> g_xc, 1 -> g_wqc, 2 -> g_wpc
// ---------------------------------------------------------------------------
__global__ __launch_bounds__(256) void cvt_tf32_kernel(
    const float* __restrict__ in, int n4, int which)
{
    float* outp = (which == 0) ? g_xc : (which == 1) ? g_wqc : g_wpc;
    int i = blockIdx.x * 256 + threadIdx.x;
    if (i >= n4) return;
    float4 v = ((const float4*)in)[i];
    uint4 r;
    r.x = tf32_bits(v.x);
    r.y = tf32_bits(v.y);
    r.z = tf32_bits(v.z);
    r.w = tf32_bits(v.w);
    ((uint4*)outp)[i] = r;
}

// ---------------------------------------------------------------------------
// tf32 mma.sync GEMM: out[M,Ntot] = A[M,768] @ W[768,Ntot] + bias
// CTA 128x128, ktile 32, cp.async double-buffered smem.
// 8 warps as 2(m) x 4(n); warp tile 64x32 = 4 m16 x 4 n8 fragments.
// As: m-major [128][36] (frag-load bank = 4g+c, perfect permutation)
// Bs: k-major [32][136] (136 = 8 mod 32 -> bank = 8c+g, perfect permutation)
// mode 0: QKV epilogue (scatter to g_q/g_k/g_v, q * 0.125)
// mode 1: row-major store to out
// ---------------------------------------------------------------------------
#define KTILE 32
#define NIT (CC / KTILE)        // 24
#define ASTRIDE 36
#define BSTRIDE 136
#define ABYTES (128 * ASTRIDE * 4)   // 18432
#define BBYTES (KTILE * BSTRIDE * 4) // 17408
#define BUFBYTES (ABYTES + BBYTES)   // 35840
#define SMEMB (2 * BUFBYTES)         // 71680

__device__ __forceinline__ void mm_issue_tile(
    const float* __restrict__ A, const float* __restrict__ W,
    uint32_t sbuf, int m0, int n0, int k0, int Ntot, int tid)
{
    const uint32_t sA = sbuf;
    const uint32_t sB = sbuf + ABYTES;
#pragma unroll
    for (int i = 0; i < 4; i++) {
        int idx = tid + 256 * i;
        int m = idx >> 3, kq = idx & 7;       // coalesced 16B chunks along k
        cp_async16(sA + (m * ASTRIDE + kq * 4) * 4,
                   A + (size_t)(m0 + m) * CC + k0 + kq * 4);
    }
#pragma unroll
    for (int i = 0; i < 4; i++) {
        int idx = tid + 256 * i;
        int n4 = idx & 31, k = idx >> 5;      // coalesced 16B chunks along n
        cp_async16(sB + (k * BSTRIDE + n4 * 4) * 4,
                   W + (size_t)(k0 + k) * Ntot + n0 + n4 * 4);
    }
    CP_COMMIT();
}

__global__ __launch_bounds__(256, 2) void mm_mma_kernel(
    const float* __restrict__ bias, float* __restrict__ out,
    int Ntot, int mode)
{
    extern __shared__ __align__(16) char smem[];
    const float* A = (mode == 0) ? g_xc : g_y;
    const float* W = (mode == 0) ? g_wqc : g_wpc;

    const int tid = threadIdx.x;
    const int wid = tid >> 5;
    const int lane = tid & 31;
    const int g = lane >> 2;       // 0..7
    const int c4 = lane & 3;       // 0..3
    const int m0 = blockIdx.y * 128;
    const int n0 = blockIdx.x * 128;
    const int wm = (wid >> 2) * 64;       // 0 or 64
    const int wn = (wid & 3) * 32;        // 0,32,64,96
    const uint32_t sbase = smem_u32(smem);

    float acc[4][4][4];
#pragma unroll
    for (int mt = 0; mt < 4; mt++)
#pragma unroll
        for (int nt = 0; nt < 4; nt++)
#pragma unroll
            for (int i = 0; i < 4; i++) acc[mt][nt][i] = 0.0f;

    mm_issue_tile(A, W, sbase, m0, n0, 0, Ntot, tid);

    for (int it = 0; it < NIT; it++) {
        const int buf = it & 1;
        if (it + 1 < NIT) {
            mm_issue_tile(A, W, sbase + (buf ^ 1) * BUFBYTES,
                          m0, n0, (it + 1) * KTILE, Ntot, tid);
            CP_WAIT(1);
        } else {
            CP_WAIT(0);
        }
        __syncthreads();

        const float* Asp = (const float*)(smem + buf * BUFBYTES);
        const float* Bsp = (const float*)(smem + buf * BUFBYTES + ABYTES);

#pragma unroll
        for (int kk = 0; kk < KTILE; kk += 8) {
            uint32_t a[4][4], b[4][2];
#pragma unroll
            for (int mt = 0; mt < 4; mt++) {
                const float* p = Asp + (wm + mt * 16 + g) * ASTRIDE + kk + c4;
                a[mt][0] = __float_as_uint(p[0]);
                a[mt][2] = __float_as_uint(p[4]);
                a[mt][1] = __float_as_uint(p[8 * ASTRIDE]);
                a[mt][3] = __float_as_uint(p[8 * ASTRIDE + 4]);
            }
#pragma unroll
            for (int nt = 0; nt < 4; nt++) {
                const float* q = Bsp + (kk + c4) * BSTRIDE + wn + nt * 8 + g;
                b[nt][0] = __float_as_uint(q[0]);
                b[nt][1] = __float_as_uint(q[4 * BSTRIDE]);
            }
#pragma unroll
            for (int mt = 0; mt < 4; mt++)
#pragma unroll
                for (int nt = 0; nt < 4; nt++)
                    mma_tf32(acc[mt][nt], a[mt], b[nt]);
        }
        __syncthreads();
    }

    // Epilogue.  Fragment (mt,nt): rows g,g+8; cols 2c,2c+1.
    if (mode == 1) {
#pragma unroll
        for (int mt = 0; mt < 4; mt++) {
#pragma unroll
            for (int nt = 0; nt < 4; nt++) {
                int mg = m0 + wm + mt * 16 + g;
                int ng = n0 + wn + nt * 8 + 2 * c4;
                float b0 = bias[ng], b1 = bias[ng + 1];
                float2 v0 = make_float2(acc[mt][nt][0] + b0, acc[mt][nt][1] + b1);
                float2 v1 = make_float2(acc[mt][nt][2] + b0, acc[mt][nt][3] + b1);
                *(float2*)(out + (size_t)mg * CC + ng) = v0;
                *(float2*)(out + (size_t)(mg + 8) * CC + ng) = v1;
            }
        }
    } else {
#pragma unroll
        for (int mt = 0; mt < 4; mt++) {
#pragma unroll
            for (int nt = 0; nt < 4; nt++) {
                int mg = m0 + wm + mt * 16 + g;
                int ng = n0 + wn + nt * 8 + 2 * c4;
                int region = ng / CC;             // 0=q 1=k 2=v
                int cp = ng - region * CC;
                int h = cp >> 6, d = cp & 63;     // d even
                float sc = (region == 0) ? 0.125f : 1.0f;
                float* base = (region == 0) ? g_q : (region == 1) ? g_k : g_v;
                int bi = mg >> 10, t = mg & 1023;
                float* dst = base + ((size_t)(bi * HH + h) * TT + t) * DD + d;
                float b0 = bias[ng], b1 = bias[ng + 1];
                float2 v0 = make_float2((acc[mt][nt][0] + b0) * sc,
                                        (acc[mt][nt][1] + b1) * sc);
                float2 v1 = make_float2((acc[mt][nt][2] + b0) * sc,
                                        (acc[mt][nt][3] + b1) * sc);
                *(float2*)dst = v0;
                *(float2*)(dst + 8 * DD) = v1;    // row mg+8, same b/h
            }
        }
    }
}

// ---------------------------------------------------------------------------
// Causal flash attention (fp32 FFMA; proven).  Epilogue rounds to tf32 so the
// proj GEMM's truncating HMMA sees RNA-rounded inputs.
// ---------------------------------------------------------------------------
__global__ __launch_bounds__(256) void attn_kernel()
{
    __shared__ __align__(16) float Qs[4096];
    __shared__ __align__(16) float KPs[4096];  // K tile, then P tile
    __shared__ __align__(16) float Vs[4096];

    const int tid = threadIdx.x;
    const int rg = tid >> 4;   // 0..15
    const int tc = tid & 15;   // 0..15
    const int qt = blockIdx.x; // 0..15
    const int bh = blockIdx.y; // 0..95
    const int q0 = qt * 64;

    const float* Qg = g_q + (size_t)bh * (TT * DD);
    const float* Kg = g_k + (size_t)bh * (TT * DD);
    const float* Vg = g_v + (size_t)bh * (TT * DD);

#pragma unroll
    for (int i = 0; i < 4; i++) {
        int f = tid + i * 256;
        int rr = f >> 4;
        int c4 = (f & 15) << 2;
        float4 v = *(const float4*)(Qg + (size_t)(q0 + rr) * DD + c4);
        int sw = rr & 15;
        int base = rr * 64;
        Qs[base + ((c4 + 0) ^ sw)] = v.x;
        Qs[base + ((c4 + 1) ^ sw)] = v.y;
        Qs[base + ((c4 + 2) ^ sw)] = v.z;
        Qs[base + ((c4 + 3) ^ sw)] = v.w;
    }

    float o[4][4];
    float m_r[4], l_r[4];
#pragma unroll
    for (int a = 0; a < 4; a++) {
        m_r[a] = -1e30f;
        l_r[a] = 0.0f;
#pragma unroll
        for (int ii = 0; ii < 4; ii++) o[a][ii] = 0.0f;
    }

    for (int j = 0; j <= qt; j++) {
        const int k0 = j * 64;
        __syncthreads();
#pragma unroll
        for (int i = 0; i < 4; i++) {
            int f = tid + i * 256;
            int rr = f >> 4;
            int c4 = (f & 15) << 2;
            float4 kv = *(const float4*)(Kg + (size_t)(k0 + rr) * DD + c4);
            int sw = rr & 15;
            int base = rr * 64;
            KPs[base + ((c4 + 0) ^ sw)] = kv.x;
            KPs[base + ((c4 + 1) ^ sw)] = kv.y;
            KPs[base + ((c4 + 2) ^ sw)] = kv.z;
            KPs[base + ((c4 + 3) ^ sw)] = kv.w;
            *(float4*)(Vs + base + c4) =
                *(const float4*)(Vg + (size_t)(k0 + rr) * DD + c4);
        }
        __syncthreads();

        float s[4][4];
#pragma unroll
        for (int a = 0; a < 4; a++)
#pragma unroll
            for (int cc = 0; cc < 4; cc++) s[a][cc] = 0.0f;

#pragma unroll 8
        for (int d = 0; d < 64; d++) {
            const int dq = d ^ rg;
            const int dk = d ^ tc;
            float qv[4], kv_[4];
#pragma unroll
            for (int a = 0; a < 4; a++) qv[a] = Qs[(rg + 16 * a) * 64 + dq];
#pragma unroll
            for (int cc = 0; cc < 4; cc++) kv_[cc] = KPs[(tc + 16 * cc) * 64 + dk];
#pragma unroll
            for (int a = 0; a < 4; a++)
#pragma unroll
                for (int cc = 0; cc < 4; cc++) s[a][cc] += qv[a] * kv_[cc];
        }
        __syncthreads();

        if (j == qt) {
#pragma unroll
            for (int a = 0; a < 4; a++) {
                int row = rg + 16 * a;
#pragma unroll
                for (int cc = 0; cc < 4; cc++) {
                    int col = tc + 16 * cc;
                    if (col > row) s[a][cc] = -1e30f;
                }
            }
        }

#pragma unroll
        for (int a = 0; a < 4; a++) {
            float mx = fmaxf(fmaxf(s[a][0], s[a][1]), fmaxf(s[a][2], s[a][3]));
#pragma unroll
            for (int off = 1; off < 16; off <<= 1)
                mx = fmaxf(mx, __shfl_xor_sync(0xffffffffu, mx, off));
            float m_new = fmaxf(m_r[a], mx);
            float corr = __expf(m_r[a] - m_new);
            float sum = 0.0f;
#pragma unroll
            for (int cc = 0; cc < 4; cc++) {
                float p = __expf(s[a][cc] - m_new);
                s[a][cc] = p;
                sum += p;
            }
#pragma unroll
            for (int off = 1; off < 16; off <<= 1)
                sum += __shfl_xor_sync(0xffffffffu, sum, off);
            l_r[a] = l_r[a] * corr + sum;
            m_r[a] = m_new;
#pragma unroll
            for (int ii = 0; ii < 4; ii++) o[a][ii] *= corr;
        }

#pragma unroll
        for (int a = 0; a < 4; a++) {
            int base = (rg + 16 * a) * 64;
#pragma unroll
            for (int cc = 0; cc < 4; cc++) {
                int col = tc + 16 * cc;
                KPs[base + (col ^ rg)] = s[a][cc];
            }
        }
        __syncwarp();

#pragma unroll 8
        for (int c = 0; c < 64; c++) {
            const int cs = c ^ rg;
            float pv[4], vv[4];
#pragma unroll
            for (int a = 0; a < 4; a++) pv[a] = KPs[(rg + 16 * a) * 64 + cs];
#pragma unroll
            for (int ii = 0; ii < 4; ii++) vv[ii] = Vs[c * 64 + tc + 16 * ii];
#pragma unroll
            for (int a = 0; a < 4; a++)
#pragma unroll
                for (int ii = 0; ii < 4; ii++) o[a][ii] += pv[a] * vv[ii];
        }
    }

    const int bidx = bh / HH;
    const int h = bh % HH;
#pragma unroll
    for (int a = 0; a < 4; a++) {
        int row = rg + 16 * a;
        int t = q0 + row;
        float inv_l = 1.0f / l_r[a];
        float* dst = g_y + ((size_t)(bidx * TT + t)) * CC + h * DD;
#pragma unroll
        for (int ii = 0; ii < 4; ii++) {
            uint32_t r = tf32_bits(o[a][ii] * inv_l);
            dst[tc + 16 * ii] = __uint_as_float(r);
        }
    }
}

// ---------------------------------------------------------------------------
extern "C" void kernel_launch(void* const* d_in, const int* in_sizes, int n_in,
                              void* d_out, int out_size)
{
    const float* x      = (const float*)d_in[0];
    const float* w_qkv  = (const float*)d_in[1];
    const float* b_qkv  = (const float*)d_in[2];
    const float* w_proj = (const float*)d_in[3];
    const float* b_proj = (const float*)d_in[4];
    float* out = (float*)d_out;

    cudaFuncSetAttribute(mm_mma_kernel,
                         cudaFuncAttributeMaxDynamicSharedMemorySize, SMEMB);

    // tf32 (RNA) rounding of GEMM inputs
    cvt_tf32_kernel<<<(NTOK * CC / 4 + 255) / 256, 256>>>(x, NTOK * CC / 4, 0);
    cvt_tf32_kernel<<<(CC * NQKV / 4 + 255) / 256, 256>>>(w_qkv, CC * NQKV / 4, 1);
    cvt_tf32_kernel<<<(CC * CC / 4 + 255) / 256, 256>>>(w_proj, CC * CC / 4, 2);

    // QKV: [8192 x 768] @ [768 x 2304]  (tensor pipe, tf32 mma.sync)
    mm_mma_kernel<<<dim3(NQKV / 128, NTOK / 128), 256, SMEMB>>>(
        b_qkv, nullptr, NQKV, 0);
    // Attention (fp32 flash)
    attn_kernel<<<dim3(TT / 64, BB * HH), 256>>>();
    // Proj: [8192 x 768] @ [768 x 768]
    mm_mma_kernel<<<dim3(CC / 128, NTOK / 128), 256, SMEMB>>>(
        b_proj, out, CC, 1);
}

// round 9
// speedup vs baseline: 3.3608x; 3.3328x over previous
#include <cuda_runtime.h>
#include <cstdint>

// Problem constants
#define BB 8
#define TT 1024
#define CC 768
#define HH 12
#define DD 64
#define NTOK (BB * TT)      // 8192
#define NQKV (3 * CC)       // 2304

// Scratch (device globals; no runtime allocation allowed)
__device__ float g_q[BB * HH * TT * DD];   // [B,H,T,D], q pre-scaled by log2e/8
__device__ float g_k[BB * HH * TT * DD];
__device__ float g_v[BB * HH * TT * DD];
__device__ float g_y[BB * TT * CC];        // attention output (tf32-rounded)
__device__ float g_xc[NTOK * CC];          // x, tf32-rounded
__device__ float g_wqc[CC * NQKV];         // w_qkv, tf32-rounded
__device__ float g_wpc[CC * CC];           // w_proj, tf32-rounded

// ---------------------------------------------------------------------------
// Helpers (compute_80-level PTX only; no sm_103a-only features)
// ---------------------------------------------------------------------------
__device__ __forceinline__ uint32_t smem_u32(const void* p) {
    uint32_t a;
    asm("{ .reg .u64 t; cvta.to.shared.u64 t, %1; cvt.u32.u64 %0, t; }"
        : "=r"(a) : "l"(p));
    return a;
}
__device__ __forceinline__ uint32_t tf32_bits(float x) {
    uint32_t r;
    asm("cvt.rna.tf32.f32 %0, %1;" : "=r"(r) : "f"(x));
    return r;
}
__device__ __forceinline__ float tf32_round(float x) {
    return __uint_as_float(tf32_bits(x));
}
__device__ __forceinline__ float ex2(float x) {
    float y;
    asm("ex2.approx.ftz.f32 %0, %1;" : "=f"(y) : "f"(x));
    return y;
}
__device__ __forceinline__ void cp_async16(uint32_t dst, const void* src) {
    asm volatile("cp.async.ca.shared.global [%0], [%1], 16;"
                 :: "r"(dst), "l"(src));
}
#define CP_COMMIT() asm volatile("cp.async.commit_group;" ::: "memory")
#define CP_WAIT(n)  asm volatile("cp.async.wait_group %0;" :: "n"(n) : "memory")

// m16n8k8 tf32 mma: D += A*B, fp32 accumulate.
__device__ __forceinline__ void mma_tf32(float* d, const uint32_t* a,
                                         const uint32_t* b) {
    asm volatile(
        "mma.sync.aligned.m16n8k8.row.col.f32.tf32.tf32.f32 "
        "{%0,%1,%2,%3}, {%4,%5,%6,%7}, {%8,%9}, {%0,%1,%2,%3};"
        : "+f"(d[0]), "+f"(d[1]), "+f"(d[2]), "+f"(d[3])
        : "r"(a[0]), "r"(a[1]), "r"(a[2]), "r"(a[3]),
          "r"(b[0]), "r"(b[1]));
}

// ---------------------------------------------------------------------------
// Elementwise tf32 rounding pass (RNA), vectorized.
// which: 0 -> g_xc, 1 -> g_wqc, 2 -> g_wpc
// ---------------------------------------------------------------------------
__global__ __launch_bounds__(256) void cvt_tf32_kernel(
    const float* __restrict__ in, int n4, int which)
{
    float* outp = (which == 0) ? g_xc : (which == 1) ? g_wqc : g_wpc;
    int i = blockIdx.x * 256 + threadIdx.x;
    if (i >= n4) return;
    float4 v = ((const float4*)in)[i];
    uint4 r;
    r.x = tf32_bits(v.x);
    r.y = tf32_bits(v.y);
    r.z = tf32_bits(v.z);
    r.w = tf32_bits(v.w);
    ((uint4*)outp)[i] = r;
}

// ---------------------------------------------------------------------------
// tf32 mma.sync GEMM: out[M,Ntot] = A[M,768] @ W[768,Ntot] + bias
// (proven R8 kernel; mode-0 epilogue now tf32-rounds q/k/v and folds log2e
//  into the q scale so attention can use ex2 directly)
// ---------------------------------------------------------------------------
#define KTILE 32
#define NIT (CC / KTILE)        // 24
#define ASTRIDE 36
#define BSTRIDE 136
#define ABYTES (128 * ASTRIDE * 4)   // 18432
#define BBYTES (KTILE * BSTRIDE * 4) // 17408
#define BUFBYTES (ABYTES + BBYTES)   // 35840
#define SMEMB (2 * BUFBYTES)         // 71680

__device__ __forceinline__ void mm_issue_tile(
    const float* __restrict__ A, const float* __restrict__ W,
    uint32_t sbuf, int m0, int n0, int k0, int Ntot, int tid)
{
    const uint32_t sA = sbuf;
    const uint32_t sB = sbuf + ABYTES;
#pragma unroll
    for (int i = 0; i < 4; i++) {
        int idx = tid + 256 * i;
        int m = idx >> 3, kq = idx & 7;
        cp_async16(sA + (m * ASTRIDE + kq * 4) * 4,
                   A + (size_t)(m0 + m) * CC + k0 + kq * 4);
    }
#pragma unroll
    for (int i = 0; i < 4; i++) {
        int idx = tid + 256 * i;
        int n4 = idx & 31, k = idx >> 5;
        cp_async16(sB + (k * BSTRIDE + n4 * 4) * 4,
                   W + (size_t)(k0 + k) * Ntot + n0 + n4 * 4);
    }
    CP_COMMIT();
}

__global__ __launch_bounds__(256, 2) void mm_mma_kernel(
    const float* __restrict__ bias, float* __restrict__ out,
    int Ntot, int mode)
{
    extern __shared__ __align__(16) char smem[];
    const float* A = (mode == 0) ? g_xc : g_y;
    const float* W = (mode == 0) ? g_wqc : g_wpc;

    const int tid = threadIdx.x;
    const int wid = tid >> 5;
    const int lane = tid & 31;
    const int g = lane >> 2;
    const int c4 = lane & 3;
    const int m0 = blockIdx.y * 128;
    const int n0 = blockIdx.x * 128;
    const int wm = (wid >> 2) * 64;
    const int wn = (wid & 3) * 32;
    const uint32_t sbase = smem_u32(smem);

    float acc[4][4][4];
#pragma unroll
    for (int mt = 0; mt < 4; mt++)
#pragma unroll
        for (int nt = 0; nt < 4; nt++)
#pragma unroll
            for (int i = 0; i < 4; i++) acc[mt][nt][i] = 0.0f;

    mm_issue_tile(A, W, sbase, m0, n0, 0, Ntot, tid);

    for (int it = 0; it < NIT; it++) {
        const int buf = it & 1;
        if (it + 1 < NIT) {
            mm_issue_tile(A, W, sbase + (buf ^ 1) * BUFBYTES,
                          m0, n0, (it + 1) * KTILE, Ntot, tid);
            CP_WAIT(1);
        } else {
            CP_WAIT(0);
        }
        __syncthreads();

        const float* Asp = (const float*)(smem + buf * BUFBYTES);
        const float* Bsp = (const float*)(smem + buf * BUFBYTES + ABYTES);

#pragma unroll
        for (int kk = 0; kk < KTILE; kk += 8) {
            uint32_t a[4][4], b[4][2];
#pragma unroll
            for (int mt = 0; mt < 4; mt++) {
                const float* p = Asp + (wm + mt * 16 + g) * ASTRIDE + kk + c4;
                a[mt][0] = __float_as_uint(p[0]);
                a[mt][2] = __float_as_uint(p[4]);
                a[mt][1] = __float_as_uint(p[8 * ASTRIDE]);
                a[mt][3] = __float_as_uint(p[8 * ASTRIDE + 4]);
            }
#pragma unroll
            for (int nt = 0; nt < 4; nt++) {
                const float* q = Bsp + (kk + c4) * BSTRIDE + wn + nt * 8 + g;
                b[nt][0] = __float_as_uint(q[0]);
                b[nt][1] = __float_as_uint(q[4 * BSTRIDE]);
            }
#pragma unroll
            for (int mt = 0; mt < 4; mt++)
#pragma unroll
                for (int nt = 0; nt < 4; nt++)
                    mma_tf32(acc[mt][nt], a[mt], b[nt]);
        }
        __syncthreads();
    }

    if (mode == 1) {
#pragma unroll
        for (int mt = 0; mt < 4; mt++) {
#pragma unroll
            for (int nt = 0; nt < 4; nt++) {
                int mg = m0 + wm + mt * 16 + g;
                int ng = n0 + wn + nt * 8 + 2 * c4;
                float b0 = bias[ng], b1 = bias[ng + 1];
                float2 v0 = make_float2(acc[mt][nt][0] + b0, acc[mt][nt][1] + b1);
                float2 v1 = make_float2(acc[mt][nt][2] + b0, acc[mt][nt][3] + b1);
                *(float2*)(out + (size_t)mg * CC + ng) = v0;
                *(float2*)(out + (size_t)(mg + 8) * CC + ng) = v1;
            }
        }
    } else {
        // q scale folds 1/sqrt(64) AND log2(e): attention softmax uses ex2.
#pragma unroll
        for (int mt = 0; mt < 4; mt++) {
#pragma unroll
            for (int nt = 0; nt < 4; nt++) {
                int mg = m0 + wm + mt * 16 + g;
                int ng = n0 + wn + nt * 8 + 2 * c4;
                int region = ng / CC;             // 0=q 1=k 2=v
                int cp = ng - region * CC;
                int h = cp >> 6, d = cp & 63;
                float sc = (region == 0) ? 0.18033688011112042f : 1.0f;
                float* base = (region == 0) ? g_q : (region == 1) ? g_k : g_v;
                int bi = mg >> 10, t = mg & 1023;
                float* dst = base + ((size_t)(bi * HH + h) * TT + t) * DD + d;
                float b0 = bias[ng], b1 = bias[ng + 1];
                float2 v0 = make_float2(tf32_round((acc[mt][nt][0] + b0) * sc),
                                        tf32_round((acc[mt][nt][1] + b1) * sc));
                float2 v1 = make_float2(tf32_round((acc[mt][nt][2] + b0) * sc),
                                        tf32_round((acc[mt][nt][3] + b1) * sc));
                *(float2*)dst = v0;
                *(float2*)(dst + 8 * DD) = v1;
            }
        }
    }
}

// ---------------------------------------------------------------------------
// Causal flash attention on tf32 mma.sync.
// CTA = 128 Q rows x one (b,h); 8 warps; warp w owns Q rows w*16..w*16+15
// (softmax rows warp-private).  KV tiles of 64, cp.async double-buffered.
// S tile per warp: m16 x 8*n8; PV: P staged via warp-private smem (stride 68
// => A-frag LDS bank = 4g+c4+kk, perfect permutation).  V stride 72 => B-frag
// bank = 8c4+g, perfect.  Q pre-scaled by log2e/8 => softmax uses ex2.
// ---------------------------------------------------------------------------
#define AKV 64
#define QSTR 68
#define KSTR 68
#define VSTR 72
#define PSTR 68
#define PS_OFF (128 * QSTR)                 // 8704
#define KV_OFF (PS_OFF + 128 * PSTR)        // 17408
#define KBUF_F (AKV * KSTR)                 // 4352
#define KVBUF_F (KBUF_F + AKV * VSTR)       // 8960
#define ATT_SMEMF (KV_OFF + 2 * KVBUF_F)    // 35328
#define ATT_SMEMB (ATT_SMEMF * 4)           // 141312

__global__ __launch_bounds__(256, 1) void attn_mma_kernel()
{
    extern __shared__ __align__(16) float sm[];
    const int tid = threadIdx.x;
    const int wid = tid >> 5;
    const int lane = tid & 31;
    const int g = lane >> 2;      // 0..7
    const int c4 = lane & 3;      // 0..3
    const int qt = 7 - (int)blockIdx.x;   // heavy tiles launch first
    const int bh = blockIdx.y;
    const int q0 = qt * 128;

    const float* Qg = g_q + (size_t)bh * (TT * DD) + (size_t)q0 * DD;
    const float* Kg = g_k + (size_t)bh * (TT * DD);
    const float* Vg = g_v + (size_t)bh * (TT * DD);
    const uint32_t sb = smem_u32(sm);

    // Prologue: Q tile (128x64) + KV tile 0, one cp.async group.
#pragma unroll
    for (int i = 0; i < 8; i++) {
        int idx = tid + 256 * i;
        int r = idx >> 4, c = (idx & 15) * 4;
        cp_async16(sb + (r * QSTR + c) * 4, Qg + r * DD + c);
    }
#pragma unroll
    for (int i = 0; i < 4; i++) {
        int idx = tid + 256 * i;
        int r = idx >> 4, c = (idx & 15) * 4;
        cp_async16(sb + (KV_OFF + r * KSTR + c) * 4, Kg + r * DD + c);
        cp_async16(sb + (KV_OFF + KBUF_F + r * VSTR + c) * 4, Vg + r * DD + c);
    }
    CP_COMMIT();

    float o[8][4];
#pragma unroll
    for (int nt = 0; nt < 8; nt++)
#pragma unroll
        for (int i = 0; i < 4; i++) o[nt][i] = 0.0f;
    float m0 = -1e30f, m1 = -1e30f, l0 = 0.0f, l1 = 0.0f;

    const int ntiles = 2 * qt + 2;

    for (int j = 0; j < ntiles; j++) {
        const int buf = j & 1;
        if (j + 1 < ntiles) {
            const float* Kg2 = Kg + (size_t)(j + 1) * AKV * DD;
            const float* Vg2 = Vg + (size_t)(j + 1) * AKV * DD;
            const uint32_t kvb = sb + (KV_OFF + (buf ^ 1) * KVBUF_F) * 4;
#pragma unroll
            for (int i = 0; i < 4; i++) {
                int idx = tid + 256 * i;
                int r = idx >> 4, c = (idx & 15) * 4;
                cp_async16(kvb + (r * KSTR + c) * 4, Kg2 + r * DD + c);
                cp_async16(kvb + (KBUF_F + r * VSTR + c) * 4, Vg2 + r * DD + c);
            }
            CP_COMMIT();
            CP_WAIT(1);
        } else {
            CP_WAIT(0);
        }
        __syncthreads();

        const float* Ksp = sm + KV_OFF + buf * KVBUF_F;
        const float* Vsp = Ksp + KBUF_F;
        const float* Qsp = sm + (wid * 16 + g) * QSTR;

        // S = Q @ K^T  (log2 domain; Q pre-scaled)
        float s[8][4];
#pragma unroll
        for (int nt = 0; nt < 8; nt++)
#pragma unroll
            for (int i = 0; i < 4; i++) s[nt][i] = 0.0f;

#pragma unroll
        for (int kk = 0; kk < 64; kk += 8) {
            uint32_t a[4];
            const float* qp = Qsp + kk + c4;
            a[0] = __float_as_uint(qp[0]);
            a[1] = __float_as_uint(qp[8 * QSTR]);
            a[2] = __float_as_uint(qp[4]);
            a[3] = __float_as_uint(qp[8 * QSTR + 4]);
#pragma unroll
            for (int nt = 0; nt < 8; nt++) {
                uint32_t b[2];
                const float* kp = Ksp + (nt * 8 + g) * KSTR + kk + c4;
                b[0] = __float_as_uint(kp[0]);
                b[1] = __float_as_uint(kp[4]);
                mma_tf32(s[nt], a, b);
            }
        }

        // Causal mask (only the two diagonal-straddling tiles need it)
        if (j >= 2 * qt) {
            const int off = q0 - j * AKV;   // 0 or -64
            const int r0 = wid * 16 + g, r1 = r0 + 8;
#pragma unroll
            for (int nt = 0; nt < 8; nt++) {
                int col = nt * 8 + 2 * c4;
                if (col     > r0 + off) s[nt][0] = -1e30f;
                if (col + 1 > r0 + off) s[nt][1] = -1e30f;
                if (col     > r1 + off) s[nt][2] = -1e30f;
                if (col + 1 > r1 + off) s[nt][3] = -1e30f;
            }
        }

        // Online softmax (rows g and g+8; quad-wide reduction)
        float mx0 = -1e30f, mx1 = -1e30f;
#pragma unroll
        for (int nt = 0; nt < 8; nt++) {
            mx0 = fmaxf(mx0, fmaxf(s[nt][0], s[nt][1]));
            mx1 = fmaxf(mx1, fmaxf(s[nt][2], s[nt][3]));
        }
        mx0 = fmaxf(mx0, __shfl_xor_sync(0xffffffffu, mx0, 1));
        mx0 = fmaxf(mx0, __shfl_xor_sync(0xffffffffu, mx0, 2));
        mx1 = fmaxf(mx1, __shfl_xor_sync(0xffffffffu, mx1, 1));
        mx1 = fmaxf(mx1, __shfl_xor_sync(0xffffffffu, mx1, 2));

        float mn0 = fmaxf(m0, mx0), mn1 = fmaxf(m1, mx1);
        float corr0 = ex2(m0 - mn0), corr1 = ex2(m1 - mn1);
        m0 = mn0; m1 = mn1;

        float sum0 = 0.0f, sum1 = 0.0f;
#pragma unroll
        for (int nt = 0; nt < 8; nt++) {
            s[nt][0] = ex2(s[nt][0] - m0);
            s[nt][1] = ex2(s[nt][1] - m0);
            s[nt][2] = ex2(s[nt][2] - m1);
            s[nt][3] = ex2(s[nt][3] - m1);
            sum0 += s[nt][0] + s[nt][1];
            sum1 += s[nt][2] + s[nt][3];
        }
        sum0 += __shfl_xor_sync(0xffffffffu, sum0, 1);
        sum0 += __shfl_xor_sync(0xffffffffu, sum0, 2);
        sum1 += __shfl_xor_sync(0xffffffffu, sum1, 1);
        sum1 += __shfl_xor_sync(0xffffffffu, sum1, 2);
        l0 = l0 * corr0 + sum0;
        l1 = l1 * corr1 + sum1;

#pragma unroll
        for (int nt = 0; nt < 8; nt++) {
            o[nt][0] *= corr0; o[nt][1] *= corr0;
            o[nt][2] *= corr1; o[nt][3] *= corr1;
        }

        // Stage P (tf32-rounded) into warp-private smem rows
        __syncwarp();
        float* Pp = sm + PS_OFF + (wid * 16 + g) * PSTR;
#pragma unroll
        for (int nt = 0; nt < 8; nt++) {
            int col = nt * 8 + 2 * c4;
            *(float2*)(Pp + col) =
                make_float2(tf32_round(s[nt][0]), tf32_round(s[nt][1]));
            *(float2*)(Pp + 8 * PSTR + col) =
                make_float2(tf32_round(s[nt][2]), tf32_round(s[nt][3]));
        }
        __syncwarp();

        // O += P @ V
        const float* Psp = sm + PS_OFF + (wid * 16 + g) * PSTR;
#pragma unroll
        for (int kk = 0; kk < 64; kk += 8) {
            uint32_t a[4];
            const float* pp = Psp + kk + c4;
            a[0] = __float_as_uint(pp[0]);
            a[1] = __float_as_uint(pp[8 * PSTR]);
            a[2] = __float_as_uint(pp[4]);
            a[3] = __float_as_uint(pp[8 * PSTR + 4]);
#pragma unroll
            for (int nt = 0; nt < 8; nt++) {
                uint32_t b[2];
                b[0] = __float_as_uint(Vsp[(kk + c4) * VSTR + nt * 8 + g]);
                b[1] = __float_as_uint(Vsp[(kk + c4 + 4) * VSTR + nt * 8 + g]);
                mma_tf32(o[nt], a, b);
            }
        }
        __syncthreads();  // all warps done with this KV buffer
    }

    // Epilogue: normalize, tf32-round (proj input), store to g_y [B,T,C]
    const float il0 = 1.0f / l0, il1 = 1.0f / l1;
    const int bi = bh / HH, h = bh % HH;
    const int r0 = q0 + wid * 16 + g;
    float* dst0 = g_y + ((size_t)(bi * TT + r0)) * CC + h * DD;
    float* dst1 = dst0 + 8 * CC;
#pragma unroll
    for (int nt = 0; nt < 8; nt++) {
        int col = nt * 8 + 2 * c4;
        *(float2*)(dst0 + col) = make_float2(tf32_round(o[nt][0] * il0),
                                             tf32_round(o[nt][1] * il0));
        *(float2*)(dst1 + col) = make_float2(tf32_round(o[nt][2] * il1),
                                             tf32_round(o[nt][3] * il1));
    }
}

// ---------------------------------------------------------------------------
extern "C" void kernel_launch(void* const* d_in, const int* in_sizes, int n_in,
                              void* d_out, int out_size)
{
    const float* x      = (const float*)d_in[0];
    const float* w_qkv  = (const float*)d_in[1];
    const float* b_qkv  = (const float*)d_in[2];
    const float* w_proj = (const float*)d_in[3];
    const float* b_proj = (const float*)d_in[4];
    float* out = (float*)d_out;

    cudaFuncSetAttribute(mm_mma_kernel,
                         cudaFuncAttributeMaxDynamicSharedMemorySize, SMEMB);
    cudaFuncSetAttribute(attn_mma_kernel,
                         cudaFuncAttributeMaxDynamicSharedMemorySize, ATT_SMEMB);

    // tf32 (RNA) rounding of GEMM inputs
    cvt_tf32_kernel<<<(NTOK * CC / 4 + 255) / 256, 256>>>(x, NTOK * CC / 4, 0);
    cvt_tf32_kernel<<<(CC * NQKV / 4 + 255) / 256, 256>>>(w_qkv, CC * NQKV / 4, 1);
    cvt_tf32_kernel<<<(CC * CC / 4 + 255) / 256, 256>>>(w_proj, CC * CC / 4, 2);

    // QKV: [8192 x 768] @ [768 x 2304]
    mm_mma_kernel<<<dim3(NQKV / 128, NTOK / 128), 256, SMEMB>>>(
        b_qkv, nullptr, NQKV, 0);
    // Attention: tf32 mma flash, 128-row Q tiles
    attn_mma_kernel<<<dim3(TT / 128, BB * HH), 256, ATT_SMEMB>>>();
    // Proj: [8192 x 768] @ [768 x 768]
    mm_mma_kernel<<<dim3(CC / 128, NTOK / 128), 256, SMEMB>>>(
        b_proj, out, CC, 1);
}